// round 1
// baseline (speedup 1.0000x reference)
#include <cuda_runtime.h>
#include <stdint.h>

// Problem constants
#define HW        512
#define IMG_PIX   (HW * HW)            // 262144
#define B_IMG     64
#define IMG_ELEMS (B_IMG * IMG_PIX)    // 16777216 floats (image output part)
#define NPERM     4096                 // B * 64 coefficients
#define NELEM     4096                 // permutation length (64*64 blocks)
#define NSAMP     250

// ---------------------------------------------------------------------------
// Scratch: permutation indices (4096 perms x 250) — static device array (no alloc)
// ---------------------------------------------------------------------------
__device__ int g_idx[NPERM * NSAMP];

// ---------------------------------------------------------------------------
// DCT-II 8x8 matrix Q (row 0 = sqrt(1/8); rows i>0 = 0.5*cos((2j+1)i*pi/16))
// ---------------------------------------------------------------------------
#define H0 0.3535533905932738f
#define H1 0.4903926402016152f
#define H2 0.4619397662556434f
#define H3 0.4157348061512726f
#define H4 0.3535533905932738f
#define H5 0.2777851165098011f
#define H6 0.1913417161825449f
#define H7 0.0975451610080641f

__constant__ float Qc[8][8] = {
    { H0,  H0,  H0,  H0,  H0,  H0,  H0,  H0},
    { H1,  H3,  H5,  H7, -H7, -H5, -H3, -H1},
    { H2,  H6, -H6, -H2, -H2, -H6,  H6,  H2},
    { H3, -H7, -H1, -H5,  H5,  H1,  H7, -H3},
    { H4, -H4, -H4,  H4,  H4, -H4, -H4,  H4},
    { H5, -H1,  H7,  H3, -H3, -H7,  H1, -H5},
    { H6, -H2,  H2, -H6, -H6,  H2, -H2,  H6},
    { H7, -H5,  H3, -H1,  H1, -H3,  H5, -H7},
};

__constant__ int ZIGc[64] = {
     0,  1,  8, 16,  9,  2,  3, 10, 17, 24, 32, 25, 18, 11,  4,  5,
    12, 19, 26, 33, 40, 48, 41, 34, 27, 20, 13,  6,  7, 14, 21, 28,
    35, 42, 49, 56, 57, 50, 43, 36, 29, 22, 15, 23, 30, 37, 44, 51,
    58, 59, 52, 45, 38, 31, 39, 46, 53, 60, 61, 54, 47, 55, 62, 63
};

// ---------------------------------------------------------------------------
// Threefry-2x32 (20 rounds) — matches JAX exactly
// ---------------------------------------------------------------------------
__device__ __forceinline__ void tf2(uint32_t k0, uint32_t k1,
                                    uint32_t& x0, uint32_t& x1) {
    const uint32_t ks2 = k0 ^ k1 ^ 0x1BD11BDAu;
    x0 += k0; x1 += k1;
#define TFR(r) { x0 += x1; x1 = (x1 << (r)) | (x1 >> (32 - (r))); x1 ^= x0; }
    TFR(13) TFR(15) TFR(26) TFR(6)   x0 += k1;  x1 += ks2 + 1u;
    TFR(17) TFR(29) TFR(16) TFR(24)  x0 += ks2; x1 += k0  + 2u;
    TFR(13) TFR(15) TFR(26) TFR(6)   x0 += k0;  x1 += k1  + 3u;
    TFR(17) TFR(29) TFR(16) TFR(24)  x0 += k1;  x1 += ks2 + 4u;
    TFR(13) TFR(15) TFR(26) TFR(6)   x0 += ks2; x1 += k0  + 5u;
#undef TFR
}

// ---------------------------------------------------------------------------
// Kernel 1: RGB->Y + 8x8 2D DCT. One thread = one 8x8 block.
// grid = 64 imgs * 4096 blocks / 256 = 1024 CTAs
// ---------------------------------------------------------------------------
__global__ void __launch_bounds__(256) dct_kernel(const float* __restrict__ x,
                                                  float* __restrict__ out) {
    int g   = blockIdx.x * 256 + threadIdx.x;   // 0 .. 262143
    int b   = g >> 12;
    int blk = g & 4095;
    int bi  = blk >> 6;
    int bj  = blk & 63;

    const float* xr = x + (size_t)b * 3 * IMG_PIX;
    const float* xg = xr + IMG_PIX;
    const float* xb = xg + IMG_PIX;
    int base = bi * 8 * HW + bj * 8;

    float T[8][8];
#pragma unroll
    for (int i = 0; i < 8; i++)
#pragma unroll
        for (int jj = 0; jj < 8; jj++) T[i][jj] = 0.0f;

#pragma unroll
    for (int k = 0; k < 8; k++) {
        int off = base + k * HW;
        float4 r0 = __ldg((const float4*)(xr + off));
        float4 r1 = __ldg((const float4*)(xr + off) + 1);
        float4 g0 = __ldg((const float4*)(xg + off));
        float4 g1 = __ldg((const float4*)(xg + off) + 1);
        float4 c0 = __ldg((const float4*)(xb + off));
        float4 c1 = __ldg((const float4*)(xb + off) + 1);

        float y[8];
        y[0] = 0.299f * r0.x + 0.587f * g0.x + 0.114f * c0.x;
        y[1] = 0.299f * r0.y + 0.587f * g0.y + 0.114f * c0.y;
        y[2] = 0.299f * r0.z + 0.587f * g0.z + 0.114f * c0.z;
        y[3] = 0.299f * r0.w + 0.587f * g0.w + 0.114f * c0.w;
        y[4] = 0.299f * r1.x + 0.587f * g1.x + 0.114f * c1.x;
        y[5] = 0.299f * r1.y + 0.587f * g1.y + 0.114f * c1.y;
        y[6] = 0.299f * r1.z + 0.587f * g1.z + 0.114f * c1.z;
        y[7] = 0.299f * r1.w + 0.587f * g1.w + 0.114f * c1.w;

#pragma unroll
        for (int i = 0; i < 8; i++) {
            float q = Qc[i][k];
#pragma unroll
            for (int jj = 0; jj < 8; jj++)
                T[i][jj] = fmaf(q, y[jj], T[i][jj]);
        }
    }

    float* o = out + (size_t)b * IMG_PIX + base;
#pragma unroll
    for (int i = 0; i < 8; i++) {
        float d[8];
#pragma unroll
        for (int l = 0; l < 8; l++) {
            float acc = 0.0f;
#pragma unroll
            for (int k = 0; k < 8; k++)
                acc = fmaf(T[i][k], Qc[l][k], acc);
            d[l] = acc;
        }
        float4* op = (float4*)(o + i * HW);
        op[0] = make_float4(d[0], d[1], d[2], d[3]);
        op[1] = make_float4(d[4], d[5], d[6], d[7]);
    }
}

// ---------------------------------------------------------------------------
// Kernel 2: JAX permutation reproduction (threefry-partitionable semantics).
//   keys[j]          = threefry((0,0), (0, j))                 [split(key(0),4096)]
//   per round:  key' = threefry(key, (0,0)); sub = threefry(key, (0,1))
//               sk[i] = y0 ^ y1 of threefry(sub, (0, i))       [random_bits 32]
//               stable ascending sort of (sk, value)
//   2 rounds; take first 250 values.
// Stability via uint64 composite: (sk << 24) | (pos << 12) | value.
// ---------------------------------------------------------------------------
__global__ void __launch_bounds__(512) perm_kernel() {
    __shared__ unsigned long long arr[NELEM];
    const int j   = blockIdx.x;
    const int tid = threadIdx.x;

    // keys[j] from top-level split of key(0) = (0,0)
    uint32_t key0 = 0u, key1 = (uint32_t)j;
    tf2(0u, 0u, key0, key1);

    for (int round = 0; round < 2; round++) {
        // key, subkey = split(key)
        uint32_t n0 = 0u, n1 = 0u; tf2(key0, key1, n0, n1);
        uint32_t s0 = 0u, s1 = 1u; tf2(key0, key1, s0, s1);
        key0 = n0; key1 = n1;

        for (int m = tid; m < NELEM; m += 512) {
            uint32_t b1 = 0u, b2 = (uint32_t)m;
            tf2(s0, s1, b1, b2);
            uint32_t sk = b1 ^ b2;                       // random_bits(.., 32, ..)
            unsigned long long val =
                (round == 0) ? (unsigned long long)m : (arr[m] & 0xFFFull);
            arr[m] = ((unsigned long long)sk << 24) |
                     ((unsigned long long)(unsigned)m << 12) | val;
        }
        __syncthreads();

        // bitonic sort, ascending
        for (int k = 2; k <= NELEM; k <<= 1) {
            for (int jj = k >> 1; jj > 0; jj >>= 1) {
                for (int i = tid; i < NELEM; i += 512) {
                    int ixj = i ^ jj;
                    if (ixj > i) {
                        unsigned long long a = arr[i];
                        unsigned long long c = arr[ixj];
                        bool up = ((i & k) == 0);
                        if ((a > c) == up) { arr[i] = c; arr[ixj] = a; }
                    }
                }
                __syncthreads();
            }
        }
    }

    if (tid < NSAMP)
        g_idx[j * NSAMP + tid] = (int)(arr[tid] & 0xFFFull);
}

// ---------------------------------------------------------------------------
// Kernel 3: gather samples directly from the DCT image in d_out.
// out2[b, z, s] = img[b, (blk/64)*8 + u, (blk%64)*8 + v], (u,v) from ZIGZAG[z]
// ---------------------------------------------------------------------------
__global__ void __launch_bounds__(256) sample_kernel(float* __restrict__ out) {
    int j = blockIdx.x;          // b*64 + z
    int s = threadIdx.x;
    if (s >= NSAMP) return;
    int b = j >> 6;
    int z = j & 63;
    int blk = g_idx[j * NSAMP + s];
    int loc = ZIGc[z];
    int u = loc >> 3, v = loc & 7;
    int bi = blk >> 6, bj = blk & 63;
    float val = out[(size_t)b * IMG_PIX + (size_t)(bi * 8 + u) * HW + bj * 8 + v];
    out[(size_t)IMG_ELEMS + (size_t)j * NSAMP + s] = val;
}

// ---------------------------------------------------------------------------
extern "C" void kernel_launch(void* const* d_in, const int* in_sizes, int n_in,
                              void* d_out, int out_size) {
    (void)in_sizes; (void)n_in; (void)out_size;
    const float* x = (const float*)d_in[0];
    float* out = (float*)d_out;

    dct_kernel<<<1024, 256>>>(x, out);
    perm_kernel<<<NPERM, 512>>>();
    sample_kernel<<<NPERM, 256>>>(out);
}

// round 2
// speedup vs baseline: 2.4289x; 2.4289x over previous
#include <cuda_runtime.h>
#include <stdint.h>

// Problem constants
#define HW        512
#define IMG_PIX   (HW * HW)            // 262144
#define B_IMG     64
#define IMG_ELEMS (B_IMG * IMG_PIX)    // 16777216 floats (image output part)
#define NPERM     4096                 // B * 64 coefficients
#define NELEM     4096                 // permutation length (64*64 blocks)
#define NSAMP     250

// Scratch: permutation indices (4096 perms x 250)
__device__ int g_idx[NPERM * NSAMP];

// ---------------------------------------------------------------------------
// DCT-II 8x8 matrix Q
// ---------------------------------------------------------------------------
#define H0 0.3535533905932738f
#define H1 0.4903926402016152f
#define H2 0.4619397662556434f
#define H3 0.4157348061512726f
#define H4 0.3535533905932738f
#define H5 0.2777851165098011f
#define H6 0.1913417161825449f
#define H7 0.0975451610080641f

__constant__ float Qc[8][8] = {
    { H0,  H0,  H0,  H0,  H0,  H0,  H0,  H0},
    { H1,  H3,  H5,  H7, -H7, -H5, -H3, -H1},
    { H2,  H6, -H6, -H2, -H2, -H6,  H6,  H2},
    { H3, -H7, -H1, -H5,  H5,  H1,  H7, -H3},
    { H4, -H4, -H4,  H4,  H4, -H4, -H4,  H4},
    { H5, -H1,  H7,  H3, -H3, -H7,  H1, -H5},
    { H6, -H2,  H2, -H6, -H6,  H2, -H2,  H6},
    { H7, -H5,  H3, -H1,  H1, -H3,  H5, -H7},
};

__constant__ int ZIGc[64] = {
     0,  1,  8, 16,  9,  2,  3, 10, 17, 24, 32, 25, 18, 11,  4,  5,
    12, 19, 26, 33, 40, 48, 41, 34, 27, 20, 13,  6,  7, 14, 21, 28,
    35, 42, 49, 56, 57, 50, 43, 36, 29, 22, 15, 23, 30, 37, 44, 51,
    58, 59, 52, 45, 38, 31, 39, 46, 53, 60, 61, 54, 47, 55, 62, 63
};

// ---------------------------------------------------------------------------
// Threefry-2x32 (20 rounds) — matches JAX exactly
// ---------------------------------------------------------------------------
__device__ __forceinline__ void tf2(uint32_t k0, uint32_t k1,
                                    uint32_t& x0, uint32_t& x1) {
    const uint32_t ks2 = k0 ^ k1 ^ 0x1BD11BDAu;
    x0 += k0; x1 += k1;
#define TFR(r) { x0 += x1; x1 = (x1 << (r)) | (x1 >> (32 - (r))); x1 ^= x0; }
    TFR(13) TFR(15) TFR(26) TFR(6)   x0 += k1;  x1 += ks2 + 1u;
    TFR(17) TFR(29) TFR(16) TFR(24)  x0 += ks2; x1 += k0  + 2u;
    TFR(13) TFR(15) TFR(26) TFR(6)   x0 += k0;  x1 += k1  + 3u;
    TFR(17) TFR(29) TFR(16) TFR(24)  x0 += k1;  x1 += ks2 + 4u;
    TFR(13) TFR(15) TFR(26) TFR(6)   x0 += ks2; x1 += k0  + 5u;
#undef TFR
}

// ---------------------------------------------------------------------------
// Kernel 1: RGB->Y + 8x8 2D DCT. One thread = one 8x8 block. (unchanged, 47us)
// ---------------------------------------------------------------------------
__global__ void __launch_bounds__(256) dct_kernel(const float* __restrict__ x,
                                                  float* __restrict__ out) {
    int g   = blockIdx.x * 256 + threadIdx.x;
    int b   = g >> 12;
    int blk = g & 4095;
    int bi  = blk >> 6;
    int bj  = blk & 63;

    const float* xr = x + (size_t)b * 3 * IMG_PIX;
    const float* xg = xr + IMG_PIX;
    const float* xb = xg + IMG_PIX;
    int base = bi * 8 * HW + bj * 8;

    float T[8][8];
#pragma unroll
    for (int i = 0; i < 8; i++)
#pragma unroll
        for (int jj = 0; jj < 8; jj++) T[i][jj] = 0.0f;

#pragma unroll
    for (int k = 0; k < 8; k++) {
        int off = base + k * HW;
        float4 r0 = __ldg((const float4*)(xr + off));
        float4 r1 = __ldg((const float4*)(xr + off) + 1);
        float4 g0 = __ldg((const float4*)(xg + off));
        float4 g1 = __ldg((const float4*)(xg + off) + 1);
        float4 c0 = __ldg((const float4*)(xb + off));
        float4 c1 = __ldg((const float4*)(xb + off) + 1);

        float y[8];
        y[0] = 0.299f * r0.x + 0.587f * g0.x + 0.114f * c0.x;
        y[1] = 0.299f * r0.y + 0.587f * g0.y + 0.114f * c0.y;
        y[2] = 0.299f * r0.z + 0.587f * g0.z + 0.114f * c0.z;
        y[3] = 0.299f * r0.w + 0.587f * g0.w + 0.114f * c0.w;
        y[4] = 0.299f * r1.x + 0.587f * g1.x + 0.114f * c1.x;
        y[5] = 0.299f * r1.y + 0.587f * g1.y + 0.114f * c1.y;
        y[6] = 0.299f * r1.z + 0.587f * g1.z + 0.114f * c1.z;
        y[7] = 0.299f * r1.w + 0.587f * g1.w + 0.114f * c1.w;

#pragma unroll
        for (int i = 0; i < 8; i++) {
            float q = Qc[i][k];
#pragma unroll
            for (int jj = 0; jj < 8; jj++)
                T[i][jj] = fmaf(q, y[jj], T[i][jj]);
        }
    }

    float* o = out + (size_t)b * IMG_PIX + base;
#pragma unroll
    for (int i = 0; i < 8; i++) {
        float d[8];
#pragma unroll
        for (int l = 0; l < 8; l++) {
            float acc = 0.0f;
#pragma unroll
            for (int k = 0; k < 8; k++)
                acc = fmaf(T[i][k], Qc[l][k], acc);
            d[l] = acc;
        }
        float4* op = (float4*)(o + i * HW);
        op[0] = make_float4(d[0], d[1], d[2], d[3]);
        op[1] = make_float4(d[4], d[5], d[6], d[7]);
    }
}

// ---------------------------------------------------------------------------
// Warp-shuffle compare-exchange for bitonic networks (64-bit values)
// ---------------------------------------------------------------------------
__device__ __forceinline__ unsigned long long ce_shfl(unsigned long long v,
                                                      int idx, int j, int k) {
    unsigned long long o = __shfl_xor_sync(0xFFFFFFFFu, v, j);
    bool keepmin = (((idx & j) == 0) == ((idx & k) == 0));
    unsigned long long mn = v < o ? v : o;
    unsigned long long mx = v < o ? o : v;
    return keepmin ? mn : mx;
}

// ---------------------------------------------------------------------------
// Kernel 2: JAX permutation via single-pass MSD bucket sort.
// Composite: (sk << 24) | (pos << 12) | val   (stable sort by (sk,pos))
// Bucket digit = top 8 bits of sk = bits [48,56) of composite.
// ---------------------------------------------------------------------------
__global__ void __launch_bounds__(512) perm_kernel() {
    __shared__ unsigned long long arr[NELEM];        // 32 KB
    __shared__ uint32_t hist[256];
    __shared__ uint32_t starts[257];
    __shared__ uint32_t cursor[256];

    const int tid  = threadIdx.x;
    const int lane = tid & 31;
    const int wid  = tid >> 5;
    const int j    = blockIdx.x;

    // keys[j] from top-level split of key(0) = (0,0)
    uint32_t key0 = 0u, key1 = (uint32_t)j;
    tf2(0u, 0u, key0, key1);

    unsigned long long c[8];

    for (int round = 0; round < 2; round++) {
        // key, subkey = split(key)
        uint32_t n0 = 0u, n1 = 0u; tf2(key0, key1, n0, n1);
        uint32_t s0 = 0u, s1 = 1u; tf2(key0, key1, s0, s1);
        key0 = n0; key1 = n1;

        // build composites in registers (reads old arr before overwrite)
#pragma unroll
        for (int q = 0; q < 8; q++) {
            int i = tid + q * 512;
            uint32_t b1 = 0u, b2 = (uint32_t)i;
            tf2(s0, s1, b1, b2);
            uint32_t sk = b1 ^ b2;
            unsigned long long val = (round == 0)
                ? (unsigned long long)i
                : (arr[i] & 0xFFFull);
            c[q] = ((unsigned long long)sk << 24) |
                   ((unsigned long long)(unsigned)i << 12) | val;
        }
        __syncthreads();

        if (tid < 256) hist[tid] = 0;
        __syncthreads();
#pragma unroll
        for (int q = 0; q < 8; q++)
            atomicAdd(&hist[(uint32_t)(c[q] >> 48)], 1u);
        __syncthreads();

        // exclusive scan of 256 bins by warp 0
        if (wid == 0) {
            uint32_t local[8], s = 0;
#pragma unroll
            for (int t = 0; t < 8; t++) { local[t] = hist[lane * 8 + t]; s += local[t]; }
            uint32_t inc = s;
#pragma unroll
            for (int off = 1; off < 32; off <<= 1) {
                uint32_t nn = __shfl_up_sync(0xFFFFFFFFu, inc, off);
                if (lane >= off) inc += nn;
            }
            uint32_t run = inc - s;
#pragma unroll
            for (int t = 0; t < 8; t++) {
                starts[lane * 8 + t] = run;
                cursor[lane * 8 + t] = run;
                run += local[t];
            }
            if (lane == 31) starts[256] = NELEM;
        }
        __syncthreads();

        // scatter into bucket regions
#pragma unroll
        for (int q = 0; q < 8; q++) {
            uint32_t d = (uint32_t)(c[q] >> 48);
            uint32_t p = atomicAdd(&cursor[d], 1u);
            arr[p] = c[q];
        }
        __syncthreads();

        // per-bucket register bitonic sort, one warp per bucket
        for (int b = wid; b < 256; b += 16) {
            int lo = (int)starts[b], hi = (int)starts[b + 1];
            int size = hi - lo;
            if (size <= 1) continue;
            unsigned long long v0 = (lane < size) ? arr[lo + lane] : ~0ULL;
            if (size <= 32) {
#pragma unroll
                for (int k = 2; k <= 32; k <<= 1)
#pragma unroll 5
                    for (int jj = k >> 1; jj > 0; jj >>= 1)
                        v0 = ce_shfl(v0, lane, jj, k);
                if (lane < size) arr[lo + lane] = v0;
            } else {
                unsigned long long v1 = (32 + lane < size) ? arr[lo + 32 + lane] : ~0ULL;
#pragma unroll
                for (int k = 2; k <= 64; k <<= 1) {
#pragma unroll 6
                    for (int jj = k >> 1; jj > 0; jj >>= 1) {
                        if (jj == 32) {
                            // only in k=64 merge; ascending: keep min in v0
                            unsigned long long mn = v0 < v1 ? v0 : v1;
                            unsigned long long mx = v0 < v1 ? v1 : v0;
                            v0 = mn; v1 = mx;
                        } else {
                            v0 = ce_shfl(v0, lane, jj, k);
                            v1 = ce_shfl(v1, lane + 32, jj, k);
                        }
                    }
                }
                if (lane < size) arr[lo + lane] = v0;
                if (32 + lane < size) arr[lo + 32 + lane] = v1;
            }
        }
        __syncthreads();
    }

    if (tid < NSAMP)
        g_idx[j * NSAMP + tid] = (int)(arr[tid] & 0xFFFull);
}

// ---------------------------------------------------------------------------
// Kernel 3: gather samples directly from the DCT image in d_out.
// ---------------------------------------------------------------------------
__global__ void __launch_bounds__(256) sample_kernel(float* __restrict__ out) {
    int j = blockIdx.x;          // b*64 + z
    int s = threadIdx.x;
    if (s >= NSAMP) return;
    int b = j >> 6;
    int z = j & 63;
    int blk = g_idx[j * NSAMP + s];
    int loc = ZIGc[z];
    int u = loc >> 3, v = loc & 7;
    int bi = blk >> 6, bj = blk & 63;
    float val = out[(size_t)b * IMG_PIX + (size_t)(bi * 8 + u) * HW + bj * 8 + v];
    out[(size_t)IMG_ELEMS + (size_t)j * NSAMP + s] = val;
}

// ---------------------------------------------------------------------------
extern "C" void kernel_launch(void* const* d_in, const int* in_sizes, int n_in,
                              void* d_out, int out_size) {
    (void)in_sizes; (void)n_in; (void)out_size;
    const float* x = (const float*)d_in[0];
    float* out = (float*)d_out;

    dct_kernel<<<1024, 256>>>(x, out);
    perm_kernel<<<NPERM, 512>>>();
    sample_kernel<<<NPERM, 256>>>(out);
}

// round 3
// speedup vs baseline: 3.6884x; 1.5185x over previous
#include <cuda_runtime.h>
#include <stdint.h>

// Problem constants
#define HW        512
#define IMG_PIX   (HW * HW)            // 262144
#define B_IMG     64
#define IMG_ELEMS (B_IMG * IMG_PIX)    // 16777216 floats (image output part)
#define NPERM     4096                 // B * 64 coefficients
#define NELEM     4096                 // permutation length (64*64 blocks)
#define NSAMP     250

// Scratch: permutation indices (4096 perms x 250)
__device__ int g_idx[NPERM * NSAMP];

// ---------------------------------------------------------------------------
// DCT-II 8x8 matrix Q
// ---------------------------------------------------------------------------
#define H0 0.3535533905932738f
#define H1 0.4903926402016152f
#define H2 0.4619397662556434f
#define H3 0.4157348061512726f
#define H4 0.3535533905932738f
#define H5 0.2777851165098011f
#define H6 0.1913417161825449f
#define H7 0.0975451610080641f

__constant__ float Qc[8][8] = {
    { H0,  H0,  H0,  H0,  H0,  H0,  H0,  H0},
    { H1,  H3,  H5,  H7, -H7, -H5, -H3, -H1},
    { H2,  H6, -H6, -H2, -H2, -H6,  H6,  H2},
    { H3, -H7, -H1, -H5,  H5,  H1,  H7, -H3},
    { H4, -H4, -H4,  H4,  H4, -H4, -H4,  H4},
    { H5, -H1,  H7,  H3, -H3, -H7,  H1, -H5},
    { H6, -H2,  H2, -H6, -H6,  H2, -H2,  H6},
    { H7, -H5,  H3, -H1,  H1, -H3,  H5, -H7},
};

__constant__ int ZIGc[64] = {
     0,  1,  8, 16,  9,  2,  3, 10, 17, 24, 32, 25, 18, 11,  4,  5,
    12, 19, 26, 33, 40, 48, 41, 34, 27, 20, 13,  6,  7, 14, 21, 28,
    35, 42, 49, 56, 57, 50, 43, 36, 29, 22, 15, 23, 30, 37, 44, 51,
    58, 59, 52, 45, 38, 31, 39, 46, 53, 60, 61, 54, 47, 55, 62, 63
};

// ---------------------------------------------------------------------------
// Threefry-2x32 (20 rounds) — matches JAX exactly (verified bit-exact)
// ---------------------------------------------------------------------------
__device__ __forceinline__ void tf2(uint32_t k0, uint32_t k1,
                                    uint32_t& x0, uint32_t& x1) {
    const uint32_t ks2 = k0 ^ k1 ^ 0x1BD11BDAu;
    x0 += k0; x1 += k1;
#define TFR(r) { x0 += x1; x1 = (x1 << (r)) | (x1 >> (32 - (r))); x1 ^= x0; }
    TFR(13) TFR(15) TFR(26) TFR(6)   x0 += k1;  x1 += ks2 + 1u;
    TFR(17) TFR(29) TFR(16) TFR(24)  x0 += ks2; x1 += k0  + 2u;
    TFR(13) TFR(15) TFR(26) TFR(6)   x0 += k0;  x1 += k1  + 3u;
    TFR(17) TFR(29) TFR(16) TFR(24)  x0 += k1;  x1 += ks2 + 4u;
    TFR(13) TFR(15) TFR(26) TFR(6)   x0 += ks2; x1 += k0  + 5u;
#undef TFR
}

// ---------------------------------------------------------------------------
// Kernel 1: RGB->Y + 8x8 2D DCT. One thread = one 8x8 block. (48us, 64% DRAM)
// ---------------------------------------------------------------------------
__global__ void __launch_bounds__(256) dct_kernel(const float* __restrict__ x,
                                                  float* __restrict__ out) {
    int g   = blockIdx.x * 256 + threadIdx.x;
    int b   = g >> 12;
    int blk = g & 4095;
    int bi  = blk >> 6;
    int bj  = blk & 63;

    const float* xr = x + (size_t)b * 3 * IMG_PIX;
    const float* xg = xr + IMG_PIX;
    const float* xb = xg + IMG_PIX;
    int base = bi * 8 * HW + bj * 8;

    float T[8][8];
#pragma unroll
    for (int i = 0; i < 8; i++)
#pragma unroll
        for (int jj = 0; jj < 8; jj++) T[i][jj] = 0.0f;

#pragma unroll
    for (int k = 0; k < 8; k++) {
        int off = base + k * HW;
        float4 r0 = __ldg((const float4*)(xr + off));
        float4 r1 = __ldg((const float4*)(xr + off) + 1);
        float4 g0 = __ldg((const float4*)(xg + off));
        float4 g1 = __ldg((const float4*)(xg + off) + 1);
        float4 c0 = __ldg((const float4*)(xb + off));
        float4 c1 = __ldg((const float4*)(xb + off) + 1);

        float y[8];
        y[0] = 0.299f * r0.x + 0.587f * g0.x + 0.114f * c0.x;
        y[1] = 0.299f * r0.y + 0.587f * g0.y + 0.114f * c0.y;
        y[2] = 0.299f * r0.z + 0.587f * g0.z + 0.114f * c0.z;
        y[3] = 0.299f * r0.w + 0.587f * g0.w + 0.114f * c0.w;
        y[4] = 0.299f * r1.x + 0.587f * g1.x + 0.114f * c1.x;
        y[5] = 0.299f * r1.y + 0.587f * g1.y + 0.114f * c1.y;
        y[6] = 0.299f * r1.z + 0.587f * g1.z + 0.114f * c1.z;
        y[7] = 0.299f * r1.w + 0.587f * g1.w + 0.114f * c1.w;

#pragma unroll
        for (int i = 0; i < 8; i++) {
            float q = Qc[i][k];
#pragma unroll
            for (int jj = 0; jj < 8; jj++)
                T[i][jj] = fmaf(q, y[jj], T[i][jj]);
        }
    }

    float* o = out + (size_t)b * IMG_PIX + base;
#pragma unroll
    for (int i = 0; i < 8; i++) {
        float d[8];
#pragma unroll
        for (int l = 0; l < 8; l++) {
            float acc = 0.0f;
#pragma unroll
            for (int k = 0; k < 8; k++)
                acc = fmaf(T[i][k], Qc[l][k], acc);
            d[l] = acc;
        }
        float4* op = (float4*)(o + i * HW);
        op[0] = make_float4(d[0], d[1], d[2], d[3]);
        op[1] = make_float4(d[4], d[5], d[6], d[7]);
    }
}

// ---------------------------------------------------------------------------
// Kernel 2: JAX permutation via MSD bucket + rank-by-scan (no sort networks).
// Composite: (sk << 24) | (pos << 12) | val  — 56-bit, all distinct.
// Digit = top 9 bits of sk = composite bits [47,56).
// Final position of element = bucket_start + #{bucket members smaller than it}.
// ---------------------------------------------------------------------------
#define NBIN 512

__global__ void __launch_bounds__(512) perm_kernel() {
    __shared__ unsigned long long arr[NELEM];        // 32 KB
    __shared__ uint32_t hist[NBIN];
    __shared__ uint32_t starts[NBIN + 1];
    __shared__ uint32_t cursor[NBIN];
    __shared__ uint32_t wsum[16];

    const int tid  = threadIdx.x;
    const int lane = tid & 31;
    const int wid  = tid >> 5;
    const int j    = blockIdx.x;

    // keys[j] from top-level split of key(0) = (0,0)
    uint32_t key0 = 0u, key1 = (uint32_t)j;
    tf2(0u, 0u, key0, key1);

    unsigned long long c[8];
    uint32_t fp[8];

    for (int round = 0; round < 2; round++) {
        // key, subkey = split(key)
        uint32_t n0 = 0u, n1 = 0u; tf2(key0, key1, n0, n1);
        uint32_t s0 = 0u, s1 = 1u; tf2(key0, key1, s0, s1);
        key0 = n0; key1 = n1;

        // build composites in registers (reads previous round's arr values)
#pragma unroll
        for (int q = 0; q < 8; q++) {
            int i = tid + q * 512;
            uint32_t b1 = 0u, b2 = (uint32_t)i;
            tf2(s0, s1, b1, b2);
            uint32_t sk = b1 ^ b2;
            unsigned long long val = (round == 0)
                ? (unsigned long long)i
                : (arr[i] & 0xFFFull);
            c[q] = ((unsigned long long)sk << 24) |
                   ((unsigned long long)(unsigned)i << 12) | val;
        }
        __syncthreads();   // all reads of old arr done

        hist[tid] = 0;
        __syncthreads();
#pragma unroll
        for (int q = 0; q < 8; q++)
            atomicAdd(&hist[(uint32_t)(c[q] >> 47) & (NBIN - 1)], 1u);
        __syncthreads();

        // exclusive scan of 512 bins (one bin per thread)
        {
            uint32_t h = hist[tid];
            uint32_t inc = h;
#pragma unroll
            for (int off = 1; off < 32; off <<= 1) {
                uint32_t nn = __shfl_up_sync(0xFFFFFFFFu, inc, off);
                if (lane >= off) inc += nn;
            }
            if (lane == 31) wsum[wid] = inc;
            __syncthreads();
            if (wid == 0) {
                uint32_t v = (lane < 16) ? wsum[lane] : 0u;
                uint32_t vi = v;
#pragma unroll
                for (int off = 1; off < 16; off <<= 1) {
                    uint32_t nn = __shfl_up_sync(0xFFFFFFFFu, vi, off);
                    if (lane >= off) vi += nn;
                }
                if (lane < 16) wsum[lane] = vi - v;   // exclusive
            }
            __syncthreads();
            uint32_t excl = inc - h + wsum[wid];
            starts[tid] = excl;
            cursor[tid] = excl;
            if (tid == 0) starts[NBIN] = NELEM;
        }
        __syncthreads();

        // scatter into bucket regions (order within bucket irrelevant)
#pragma unroll
        for (int q = 0; q < 8; q++) {
            uint32_t d = (uint32_t)(c[q] >> 47) & (NBIN - 1);
            uint32_t p = atomicAdd(&cursor[d], 1u);
            arr[p] = c[q];
        }
        __syncthreads();

        // rank-by-scan: exact final position within bucket
#pragma unroll
        for (int q = 0; q < 8; q++) {
            uint32_t d = (uint32_t)(c[q] >> 47) & (NBIN - 1);
            uint32_t lo = starts[d], hi = starts[d + 1];
            uint32_t r = 0;
            for (uint32_t m = lo; m < hi; m++)
                r += (arr[m] < c[q]);
            fp[q] = lo + r;
        }
        __syncthreads();   // all rank reads done before overwrite

        // place in final sorted position
#pragma unroll
        for (int q = 0; q < 8; q++)
            arr[fp[q]] = c[q];
        __syncthreads();
    }

    if (tid < NSAMP)
        g_idx[j * NSAMP + tid] = (int)(arr[tid] & 0xFFFull);
}

// ---------------------------------------------------------------------------
// Kernel 3: gather samples directly from the DCT image in d_out.
// ---------------------------------------------------------------------------
__global__ void __launch_bounds__(256) sample_kernel(float* __restrict__ out) {
    int j = blockIdx.x;          // b*64 + z
    int s = threadIdx.x;
    if (s >= NSAMP) return;
    int b = j >> 6;
    int z = j & 63;
    int blk = g_idx[j * NSAMP + s];
    int loc = ZIGc[z];
    int u = loc >> 3, v = loc & 7;
    int bi = blk >> 6, bj = blk & 63;
    float val = out[(size_t)b * IMG_PIX + (size_t)(bi * 8 + u) * HW + bj * 8 + v];
    out[(size_t)IMG_ELEMS + (size_t)j * NSAMP + s] = val;
}

// ---------------------------------------------------------------------------
extern "C" void kernel_launch(void* const* d_in, const int* in_sizes, int n_in,
                              void* d_out, int out_size) {
    (void)in_sizes; (void)n_in; (void)out_size;
    const float* x = (const float*)d_in[0];
    float* out = (float*)d_out;

    dct_kernel<<<1024, 256>>>(x, out);
    perm_kernel<<<NPERM, 512>>>();
    sample_kernel<<<NPERM, 256>>>(out);
}